// round 3
// baseline (speedup 1.0000x reference)
#include <cuda_runtime.h>
#include <math.h>

// Problem dims
#define Bq   8
#define Tq   1024
#define Dq   4096
#define Hq   4
#define HSq  1024
#define BT   8192          // B*T
#define FFq  20480         // 5*D

// ---------------- scratch (__device__ globals; no allocations) ----------------
__device__ float g_q   [(size_t)Hq*BT*HSq];     // [H][B*T][HS]
__device__ float g_k   [(size_t)Hq*BT*HSq];
__device__ float g_v   [(size_t)Hq*BT*HSq];
__device__ float g_w   [(size_t)Hq*Bq*Tq*Tq];   // [H][B][T][T]
__device__ float g_ocat[(size_t)BT*Dq];         // [B][T][H*HS]
__device__ float g_srcA[(size_t)BT*Dq];
__device__ float g_wp  [(size_t)Hq*BT*Dq];      // [H][B*T][D]
__device__ float g_o2  [(size_t)BT*Dq];         // [B][T][H*T]
__device__ float g_o3  [(size_t)BT*Dq];
__device__ float g_trgf[(size_t)BT*Dq];
__device__ float g_ln2 [(size_t)BT*Dq];
__device__ float g_h1  [(size_t)BT*FFq];
__device__ float g_ff  [(size_t)BT*Dq];

__device__ __forceinline__ float gelu_exact(float x) {
    return 0.5f * x * (1.0f + erff(x * 0.70710678118654752440f));
}

// ---------------- generic batched SGEMM: C = alpha*A@op(B) (+bias) (+gelu) ---
// A: [M,K] row-major (lda=K). B: NN -> [K,N] (ldb=N); NT -> [N,K] (ldb=K).
// C row stride = ldc. Batch z = z1*batch2 + z2 with independent strides.
// 128x128x8 tile, 256 threads, 8x8 per thread.
template<bool TB>
__global__ __launch_bounds__(256, 2)
void sgemm(const float* __restrict__ A, const float* __restrict__ B,
           const float* __restrict__ bias, float* __restrict__ C,
           int M, int N, int K, int ldc, int batch2,
           long sA1, long sA2, long sB1, long sB2, long sC1, long sC2, long sBias1,
           float alpha, int act)
{
    int z  = blockIdx.z;
    int z1 = z / batch2, z2 = z % batch2;
    A += z1 * sA1 + z2 * sA2;
    B += z1 * sB1 + z2 * sB2;
    C += z1 * sC1 + z2 * sC2;
    if (bias) bias += z1 * sBias1;

    __shared__ float As[8][132];
    __shared__ float Bs[8][132];

    int tid  = threadIdx.x;
    int brow = blockIdx.y * 128;
    int bcol = blockIdx.x * 128;
    int lr = tid >> 1;            // 0..127
    int lc = (tid & 1) * 4;       // 0 or 4
    int ty = tid >> 4, tx = tid & 15;

    float acc[8][8];
#pragma unroll
    for (int i = 0; i < 8; i++)
#pragma unroll
        for (int j = 0; j < 8; j++) acc[i][j] = 0.f;

    for (int k0 = 0; k0 < K; k0 += 8) {
        float4 av = *(const float4*)(A + (long)(brow + lr) * K + k0 + lc);
        As[lc + 0][lr] = av.x; As[lc + 1][lr] = av.y;
        As[lc + 2][lr] = av.z; As[lc + 3][lr] = av.w;
        if (TB) {
            float4 bv = *(const float4*)(B + (long)(bcol + lr) * K + k0 + lc);
            Bs[lc + 0][lr] = bv.x; Bs[lc + 1][lr] = bv.y;
            Bs[lc + 2][lr] = bv.z; Bs[lc + 3][lr] = bv.w;
        } else {
            int br = tid >> 5, bc = (tid & 31) * 4;
            *(float4*)&Bs[br][bc] = *(const float4*)(B + (long)(k0 + br) * N + bcol + bc);
        }
        __syncthreads();
#pragma unroll
        for (int kk = 0; kk < 8; kk++) {
            float ra[8], rb[8];
            *(float4*)&ra[0] = *(float4*)&As[kk][ty * 4];
            *(float4*)&ra[4] = *(float4*)&As[kk][64 + ty * 4];
            *(float4*)&rb[0] = *(float4*)&Bs[kk][tx * 4];
            *(float4*)&rb[4] = *(float4*)&Bs[kk][64 + tx * 4];
#pragma unroll
            for (int i = 0; i < 8; i++)
#pragma unroll
                for (int j = 0; j < 8; j++)
                    acc[i][j] += ra[i] * rb[j];
        }
        __syncthreads();
    }

#pragma unroll
    for (int i = 0; i < 8; i++) {
        int row = brow + ((i < 4) ? (ty * 4 + i) : (64 + ty * 4 + i - 4));
#pragma unroll
        for (int j = 0; j < 8; j++) {
            int col = bcol + ((j < 4) ? (tx * 4 + j) : (64 + tx * 4 + j - 4));
            float val = acc[i][j] * alpha;
            if (bias) val += bias[col];
            if (act == 1) val = gelu_exact(val);
            C[(long)row * ldc + col] = val;
        }
    }
}

// ---------------- causal softmax over rows of [H*B*T, T] ---------------------
__global__ void softmax_causal(float* __restrict__ w)
{
    long row = blockIdx.x;
    int  t   = (int)(row % Tq);
    float* p = w + row * (long)Tq;
    int tid = threadIdx.x;
    __shared__ float red[256];

    float vals[4];
    float vmax = -1e30f;
#pragma unroll
    for (int i = 0; i < 4; i++) {
        int j = tid + i * 256;
        float x = p[j];
        vals[i] = x;
        if (j <= t && x > vmax) vmax = x;
    }
    red[tid] = vmax; __syncthreads();
    for (int s = 128; s > 0; s >>= 1) {
        if (tid < s) red[tid] = fmaxf(red[tid], red[tid + s]);
        __syncthreads();
    }
    vmax = red[0]; __syncthreads();

    float sum = 0.f;
#pragma unroll
    for (int i = 0; i < 4; i++) {
        int j = tid + i * 256;
        float e = (j <= t) ? expf(vals[i] - vmax) : 0.f;
        vals[i] = e; sum += e;
    }
    red[tid] = sum; __syncthreads();
    for (int s = 128; s > 0; s >>= 1) {
        if (tid < s) red[tid] += red[tid + s];
        __syncthreads();
    }
    float inv = 1.f / red[0];
#pragma unroll
    for (int i = 0; i < 4; i++) p[tid + i * 256] = vals[i] * inv;
}

// ------------- residual + LayerNorm: t = x (+ y); out = t+ln(t) or ln(t) -----
__global__ void resln(const float* __restrict__ x, const float* __restrict__ y,
                      const float* __restrict__ g, const float* __restrict__ b,
                      float* __restrict__ out, int ln_only)
{
    long row = blockIdx.x;
    int tid = threadIdx.x;
    const float* px = x + row * (long)Dq;
    const float* py = y ? (y + row * (long)Dq) : nullptr;
    __shared__ float sh[Dq];
    __shared__ float red[256];

    float lsum = 0.f;
    for (int i = tid; i < Dq; i += 256) {
        float t = px[i] + (py ? py[i] : 0.f);
        sh[i] = t; lsum += t;
    }
    red[tid] = lsum; __syncthreads();
    for (int s = 128; s > 0; s >>= 1) { if (tid < s) red[tid] += red[tid + s]; __syncthreads(); }
    float mean = red[0] * (1.0f / Dq);
    __syncthreads();

    float lvar = 0.f;
    for (int i = tid; i < Dq; i += 256) { float d = sh[i] - mean; lvar += d * d; }
    red[tid] = lvar; __syncthreads();
    for (int s = 128; s > 0; s >>= 1) { if (tid < s) red[tid] += red[tid + s]; __syncthreads(); }
    float rstd = rsqrtf(red[0] * (1.0f / Dq) + 1e-5f);

    float* po = out + row * (long)Dq;
    for (int i = tid; i < Dq; i += 256) {
        float t = sh[i];
        float l = (t - mean) * rstd * g[i] + b[i];
        po[i] = ln_only ? l : (t + l);
    }
}

// -----------------------------------------------------------------------------
extern "C" void kernel_launch(void* const* d_in, const int* in_sizes, int n_in,
                              void* d_out, int out_size)
{
    const float* src = (const float*)d_in[0];
    const float* att = (const float*)d_in[1];
    const float* mWq = (const float*)d_in[2];
    const float* mbq = (const float*)d_in[3];
    const float* mWk = (const float*)d_in[4];
    const float* mbk = (const float*)d_in[5];
    const float* mWv = (const float*)d_in[6];
    const float* dWp = (const float*)d_in[7];
    const float* dbp = (const float*)d_in[8];
    const float* dWo = (const float*)d_in[9];
    const float* dbo = (const float*)d_in[10];
    const float* fW1 = (const float*)d_in[11];
    const float* fb1 = (const float*)d_in[12];
    const float* fW2 = (const float*)d_in[13];
    const float* fb2 = (const float*)d_in[14];
    const float* g1  = (const float*)d_in[15];
    const float* b1  = (const float*)d_in[16];
    const float* g2  = (const float*)d_in[17];
    const float* b2  = (const float*)d_in[18];
    float* out = (float*)d_out;

    float *q, *k, *v, *w, *ocat, *srcA, *wp, *o2, *o3, *trgf, *ln2, *h1, *ff;
    cudaGetSymbolAddress((void**)&q,    g_q);
    cudaGetSymbolAddress((void**)&k,    g_k);
    cudaGetSymbolAddress((void**)&v,    g_v);
    cudaGetSymbolAddress((void**)&w,    g_w);
    cudaGetSymbolAddress((void**)&ocat, g_ocat);
    cudaGetSymbolAddress((void**)&srcA, g_srcA);
    cudaGetSymbolAddress((void**)&wp,   g_wp);
    cudaGetSymbolAddress((void**)&o2,   g_o2);
    cudaGetSymbolAddress((void**)&o3,   g_o3);
    cudaGetSymbolAddress((void**)&trgf, g_trgf);
    cudaGetSymbolAddress((void**)&ln2,  g_ln2);
    cudaGetSymbolAddress((void**)&h1,   g_h1);
    cudaGetSymbolAddress((void**)&ff,   g_ff);

    dim3 blk(256);
    const long BTHS = (long)BT * HSq;     // 8388608
    const long THS  = (long)Tq * HSq;     // 1048576
    const long BTT  = (long)Bq * Tq * Tq; // 8388608
    const long TT   = (long)Tq * Tq;      // 1048576
    const long BTD  = (long)BT * Dq;      // 33554432
    const long TD   = (long)Tq * Dq;      // 4194304
    const long WHS  = (long)Dq * HSq;     // per-head weight stride (mW*)
    const long WPD  = (long)HSq * Dq;     // per-head dWp stride

    // 1-3) Q,K,V projections per head: [8192,4096]@[4096,1024]
    {
        dim3 grd(HSq / 128, BT / 128, Hq);
        sgemm<false><<<grd, blk>>>(src, mWq, mbq, q, BT, HSq, Dq, HSq, 1,
                                   0, 0, WHS, 0, BTHS, 0, HSq, 1.0f, 0);
        sgemm<false><<<grd, blk>>>(src, mWk, mbk, k, BT, HSq, Dq, HSq, 1,
                                   0, 0, WHS, 0, BTHS, 0, HSq, 1.0f, 0);
        sgemm<false><<<grd, blk>>>(src, mWv, nullptr, v, BT, HSq, Dq, HSq, 1,
                                   0, 0, WHS, 0, BTHS, 0, 0, 1.0f, 0);
    }
    // 4) scores: per (h,b): [1024,1024] = q@k^T * sqrt(HS)
    {
        dim3 grd(Tq / 128, Tq / 128, Hq * Bq);
        sgemm<true><<<grd, blk>>>(q, k, nullptr, w, Tq, Tq, HSq, Tq, Bq,
                                  BTHS, THS, BTHS, THS, BTT, TT, 0, 32.0f, 0);
    }
    // 5) causal softmax
    softmax_causal<<<Hq * Bq * Tq, blk>>>(w);
    // 6) o = a@v, written to concatenated layout [B][T][h*HS+e]
    {
        dim3 grd(HSq / 128, Tq / 128, Hq * Bq);
        sgemm<false><<<grd, blk>>>(w, v, nullptr, ocat, Tq, HSq, Tq, Dq, Bq,
                                   BTT, TT, BTHS, THS, (long)HSq, TD, 0, 1.0f, 0);
    }
    // 7) srcA = (src+o) + ln(src+o)
    resln<<<BT, blk>>>(src, ocat, g1, b1, srcA, 0);
    // 8) wp[h] = att@dWp[h] + dbp[h]: [8192,1024]@[1024,4096]
    {
        dim3 grd(Dq / 128, BT / 128, Hq);
        sgemm<false><<<grd, blk>>>(att, dWp, dbp, wp, BT, Dq, HSq, Dq, 1,
                                   0, 0, WPD, 0, BTD, 0, Dq, 1.0f, 0);
    }
    // 9) o2 = wp@srcA^T per (h,b), written to [B][T][h*T+u]
    {
        dim3 grd(Tq / 128, Tq / 128, Hq * Bq);
        sgemm<true><<<grd, blk>>>(wp, srcA, nullptr, o2, Tq, Tq, Dq, Dq, Bq,
                                  BTD, TD, 0, TD, (long)Tq, TD, 0, 1.0f, 0);
    }
    // 10) o3 = o2@dWo + dbo
    {
        dim3 grd(Dq / 128, BT / 128, 1);
        sgemm<false><<<grd, blk>>>(o2, dWo, dbo, o3, BT, Dq, Dq, Dq, 1,
                                   0, 0, 0, 0, 0, 0, 0, 1.0f, 0);
    }
    // 11) trg_f = (srcA+o3) + ln(srcA+o3)
    resln<<<BT, blk>>>(srcA, o3, g1, b1, trgf, 0);
    // 12) ln2 = ln(trg_f, g2, b2)
    resln<<<BT, blk>>>(trgf, nullptr, g2, b2, ln2, 1);
    // 13) h1 = gelu(ln2@fW1 + fb1): [8192,4096]@[4096,20480]
    {
        dim3 grd(FFq / 128, BT / 128, 1);
        sgemm<false><<<grd, blk>>>(ln2, fW1, fb1, h1, BT, FFq, Dq, FFq, 1,
                                   0, 0, 0, 0, 0, 0, 0, 1.0f, 1);
    }
    // 14) ff = h1@fW2 + fb2: [8192,20480]@[20480,4096]
    {
        dim3 grd(Dq / 128, BT / 128, 1);
        sgemm<false><<<grd, blk>>>(h1, fW2, fb2, ff, BT, Dq, FFq, Dq, 1,
                                   0, 0, 0, 0, 0, 0, 0, 1.0f, 0);
    }
    // 15) out = ln(trg_f + ff, g2, b2)
    resln<<<BT, blk>>>(trgf, ff, g2, b2, out, 1);
}

// round 5
// speedup vs baseline: 3.0426x; 3.0426x over previous
#include <cuda_runtime.h>
#include <cuda_bf16.h>
#include <math.h>
#include <stdint.h>

typedef __nv_bfloat16 bf16;

#define Bq 8
#define Tq 1024
#define Dq 4096
#define Hq 4
#define HSq 1024
#define BT 8192
#define FFq 20480

// ----------------------------- scratch --------------------------------------
__device__ bf16 g_srcH[(size_t)BT*Dq], g_srcL[(size_t)BT*Dq];
__device__ bf16 g_attH[(size_t)BT*HSq], g_attL[(size_t)BT*HSq];
__device__ bf16 g_WqTH[(size_t)Hq*HSq*Dq], g_WqTL[(size_t)Hq*HSq*Dq];
__device__ bf16 g_WkTH[(size_t)Hq*HSq*Dq], g_WkTL[(size_t)Hq*HSq*Dq];
__device__ bf16 g_WvTH[(size_t)Hq*HSq*Dq], g_WvTL[(size_t)Hq*HSq*Dq];
__device__ bf16 g_qH[(size_t)Hq*BT*HSq], g_qL[(size_t)Hq*BT*HSq];
__device__ bf16 g_kH[(size_t)Hq*BT*HSq], g_kL[(size_t)Hq*BT*HSq];
__device__ float g_v[(size_t)Hq*BT*HSq];
__device__ bf16 g_vTH[(size_t)Hq*BT*HSq], g_vTL[(size_t)Hq*BT*HSq];
__device__ float g_w[(size_t)Hq*Bq*Tq*Tq];
__device__ bf16 g_aH[(size_t)Hq*Bq*Tq*Tq], g_aL[(size_t)Hq*Bq*Tq*Tq];
__device__ float g_ocat[(size_t)BT*Dq];
__device__ float g_srcA[(size_t)BT*Dq];
__device__ bf16 g_srcAH[(size_t)BT*Dq], g_srcAL[(size_t)BT*Dq];
__device__ bf16 g_dWpTH[(size_t)Hq*Dq*HSq], g_dWpTL[(size_t)Hq*Dq*HSq];
__device__ bf16 g_wpH[(size_t)Hq*BT*Dq], g_wpL[(size_t)Hq*BT*Dq];
__device__ bf16 g_o2H[(size_t)BT*Dq], g_o2L[(size_t)BT*Dq];
__device__ bf16 g_dWoTH[(size_t)Dq*Dq], g_dWoTL[(size_t)Dq*Dq];
__device__ float g_o3[(size_t)BT*Dq];
__device__ float g_trgf[(size_t)BT*Dq];
__device__ bf16 g_ln2H[(size_t)BT*Dq], g_ln2L[(size_t)BT*Dq];
__device__ bf16 g_fW1TH[(size_t)FFq*Dq], g_fW1TL[(size_t)FFq*Dq];
__device__ bf16 g_h1H[(size_t)BT*FFq], g_h1L[(size_t)BT*FFq];
__device__ bf16 g_fW2TH[(size_t)Dq*FFq], g_fW2TL[(size_t)Dq*FFq];
__device__ float g_ff[(size_t)BT*Dq];

// ----------------------------- helpers --------------------------------------
__device__ __forceinline__ uint32_t smem_u32(const void* p) {
    uint32_t a;
    asm("{ .reg .u64 t; cvta.to.shared.u64 t, %1; cvt.u32.u64 %0, t; }" : "=r"(a) : "l"(p));
    return a;
}
#define CPA16(dst, src) asm volatile("cp.async.cg.shared.global [%0], [%1], 16;" :: "r"((uint32_t)(dst)), "l"(src) : "memory")
#define CP_COMMIT()     asm volatile("cp.async.commit_group;" ::: "memory")
#define CP_WAIT1()      asm volatile("cp.async.wait_group 1;" ::: "memory")
#define LDSM4(r, a) asm volatile("ldmatrix.sync.aligned.m8n8.x4.shared.b16 {%0,%1,%2,%3}, [%4];" \
    : "=r"((r)[0]), "=r"((r)[1]), "=r"((r)[2]), "=r"((r)[3]) : "r"(a))
__device__ __forceinline__ void mma16816(float* d, const uint32_t* a, uint32_t b0, uint32_t b1) {
    asm volatile("mma.sync.aligned.m16n8k16.row.col.f32.bf16.bf16.f32 "
        "{%0,%1,%2,%3}, {%4,%5,%6,%7}, {%8,%9}, {%0,%1,%2,%3};"
        : "+f"(d[0]), "+f"(d[1]), "+f"(d[2]), "+f"(d[3])
        : "r"(a[0]), "r"(a[1]), "r"(a[2]), "r"(a[3]), "r"(b0), "r"(b1));
}
__device__ __forceinline__ float gelu_exact(float x) { return 0.5f*x*(1.0f+erff(x*0.70710678118654752440f)); }
__device__ __forceinline__ void split_bf(float x, bf16& h, bf16& l) {
    h = __float2bfloat16(x); l = __float2bfloat16(x - __bfloat162float(h));
}

#define SST   98304      // stage: Ah 16K | Al 16K | Bh 32K | Bl 32K
#define SMEMT 196608

// ============ mma.sync split-bf16 GEMM: C = act(alpha*A@B^T + bias) ==========
// A rows [*,K] hi/lo bf16, B rows [*,K] hi/lo bf16 (row stride == K).
// CTA tile 128x256 (8 warps, warp tile 64x64), K-chunk 64, cp.async 2-stage.
__global__ void __launch_bounds__(256, 1)
gemm_tc(const bf16* __restrict__ Ah, const bf16* __restrict__ Al,
        const bf16* __restrict__ Bh, const bf16* __restrict__ Bl,
        const float* __restrict__ bias, float* __restrict__ C,
        bf16* __restrict__ Ch, bf16* __restrict__ Cl,
        int K, int ldc, int batch2, int aR1, int aR2, int bR1, int bR2,
        long sC1, long sC2, long sB1, float alpha, int act)
{
    extern __shared__ __align__(1024) char sm[];
    uint32_t sb = smem_u32(sm);
    int tid = threadIdx.x, wid = tid >> 5, lane = tid & 31;
    int z = blockIdx.z, z1 = z / batch2, z2 = z % batch2;
    long aOff = (long)z1*aR1 + (long)z2*aR2 + blockIdx.y*128;
    long bOff = (long)z1*bR1 + (long)z2*bR2 + blockIdx.x*256;
    int warp_m = (wid & 1) * 64, warp_n = (wid >> 1) * 64;

    float acc[4][8][4];
#pragma unroll
    for (int mt = 0; mt < 4; mt++)
#pragma unroll
        for (int nt = 0; nt < 8; nt++)
#pragma unroll
            for (int r = 0; r < 4; r++) acc[mt][nt][r] = 0.f;

    int nkt = K >> 6;
    // ---- stage loader ----
    auto load_stage = [&](int s, int kt) {
        uint32_t base = sb + s * SST;
        long kb = (long)kt * 64;
#pragma unroll
        for (int it = 0; it < 4; it++) {          // A: 128 rows x 8 c16
            int idx = tid + it * 256;
            int r = idx >> 3, c = idx & 7;
            uint32_t off = (uint32_t)(r * 128 + ((c ^ (r & 7)) << 4));
            long gi = (aOff + r) * (long)K + kb + c * 8;
            CPA16(base + off,         Ah + gi);
            CPA16(base + 16384 + off, Al + gi);
        }
#pragma unroll
        for (int it = 0; it < 8; it++) {          // B: 256 rows x 8 c16
            int idx = tid + it * 256;
            int r = idx >> 3, c = idx & 7;
            uint32_t off = (uint32_t)(r * 128 + ((c ^ (r & 7)) << 4));
            long gi = (bOff + r) * (long)K + kb + c * 8;
            CPA16(base + 32768 + off, Bh + gi);
            CPA16(base + 65536 + off, Bl + gi);
        }
    };

    load_stage(0, 0);
    CP_COMMIT();

    for (int kt = 0; kt < nkt; kt++) {
        int s = kt & 1;
        if (kt + 1 < nkt) load_stage(s ^ 1, kt + 1);
        CP_COMMIT();
        CP_WAIT1();
        __syncthreads();

        uint32_t sA_h = sb + s * SST, sA_l = sA_h + 16384;
        uint32_t sB_h = sA_h + 32768, sB_l = sA_h + 65536;
#pragma unroll
        for (int ks = 0; ks < 4; ks++) {
            uint32_t ah[4][4], al[4][4];
#pragma unroll
            for (int mt = 0; mt < 4; mt++) {
                int row = warp_m + mt * 16 + (lane & 15);
                int c16 = ks * 2 + (lane >> 4);
                uint32_t off = (uint32_t)(row * 128 + ((c16 ^ (row & 7)) << 4));
                LDSM4(ah[mt], sA_h + off);
                LDSM4(al[mt], sA_l + off);
            }
#pragma unroll
            for (int p = 0; p < 4; p++) {
                int row = warp_n + p * 16 + ((lane >> 4) << 3) + (lane & 7);
                int c16 = ks * 2 + ((lane >> 3) & 1);
                uint32_t off = (uint32_t)(row * 128 + ((c16 ^ (row & 7)) << 4));
                uint32_t bh[4], bl[4];
                LDSM4(bh, sB_h + off);
                LDSM4(bl, sB_l + off);
#pragma unroll
                for (int mt = 0; mt < 4; mt++) {
                    mma16816(acc[mt][2*p],   ah[mt], bh[0], bh[1]);
                    mma16816(acc[mt][2*p],   al[mt], bh[0], bh[1]);
                    mma16816(acc[mt][2*p],   ah[mt], bl[0], bl[1]);
                    mma16816(acc[mt][2*p+1], ah[mt], bh[2], bh[3]);
                    mma16816(acc[mt][2*p+1], al[mt], bh[2], bh[3]);
                    mma16816(acc[mt][2*p+1], ah[mt], bl[2], bl[3]);
                }
            }
        }
        __syncthreads();
    }

    // ---- epilogue ----
    float* Cp = C ? C + z1*sC1 + z2*sC2 : nullptr;
    bf16 *Chp = nullptr, *Clp = nullptr;
    if (Ch) { Chp = Ch + z1*sC1 + z2*sC2; Clp = Cl + z1*sC1 + z2*sC2; }
    const float* bp = bias ? bias + z1*sB1 : nullptr;
    int rowBase = blockIdx.y*128 + warp_m + (lane >> 2);
    int colBase = blockIdx.x*256 + warp_n + (lane & 3) * 2;
#pragma unroll
    for (int mt = 0; mt < 4; mt++) {
#pragma unroll
        for (int nt = 0; nt < 8; nt++) {
#pragma unroll
            for (int hh = 0; hh < 2; hh++) {
                int row = rowBase + mt * 16 + hh * 8;
                int col = colBase + nt * 8;
                float x0 = acc[mt][nt][hh*2]     * alpha;
                float x1 = acc[mt][nt][hh*2 + 1] * alpha;
                if (bp) { x0 += bp[col]; x1 += bp[col + 1]; }
                if (act) { x0 = gelu_exact(x0); x1 = gelu_exact(x1); }
                long o = (long)row * ldc + col;
                if (Cp) *(float2*)(Cp + o) = make_float2(x0, x1);
                if (Chp) {
                    bf16 h0, l0, h1, l1;
                    split_bf(x0, h0, l0); split_bf(x1, h1, l1);
                    *(__nv_bfloat162*)(Chp + o) = __halves2bfloat162(h0, h1);
                    *(__nv_bfloat162*)(Clp + o) = __halves2bfloat162(l0, l1);
                }
            }
        }
    }
}

// ---------------- fp32 -> (hi,lo) bf16 --------------------------------------
__global__ void conv_hl(const float4* __restrict__ x, bf16* __restrict__ h, bf16* __restrict__ l) {
    long i = (long)blockIdx.x*256 + threadIdx.x;
    float4 v = x[i];
    bf16 h0,l0,h1,l1,h2,l2,h3,l3;
    split_bf(v.x,h0,l0); split_bf(v.y,h1,l1); split_bf(v.z,h2,l2); split_bf(v.w,h3,l3);
    __nv_bfloat162* hp = (__nv_bfloat162*)(h + 4*i);
    __nv_bfloat162* lp = (__nv_bfloat162*)(l + 4*i);
    hp[0]=__halves2bfloat162(h0,h1); hp[1]=__halves2bfloat162(h2,h3);
    lp[0]=__halves2bfloat162(l0,l1); lp[1]=__halves2bfloat162(l2,l3);
}

// ------------- transpose+split: in[z][R][Cc] -> out[z][Cc][R] ----------------
__global__ void tconv(const float* __restrict__ in, bf16* __restrict__ oh, bf16* __restrict__ ol, int R, int Cc) {
    __shared__ float t[32][33];
    long base = (long)blockIdx.z * R * Cc;
    int c0 = blockIdx.x*32, r0 = blockIdx.y*32;
#pragma unroll
    for (int i = 0; i < 4; i++)
        t[threadIdx.y + i*8][threadIdx.x] = in[base + (long)(r0 + threadIdx.y + i*8)*Cc + c0 + threadIdx.x];
    __syncthreads();
#pragma unroll
    for (int i = 0; i < 4; i++) {
        int c = c0 + threadIdx.y + i*8, r = r0 + threadIdx.x;
        bf16 h, l; split_bf(t[threadIdx.x][threadIdx.y + i*8], h, l);
        long o = base + (long)c*R + r;
        oh[o] = h; ol[o] = l;
    }
}

// ------------------ causal softmax -> (hi,lo) bf16 ---------------------------
__global__ void softmax_causal(const float* __restrict__ w, bf16* __restrict__ aH, bf16* __restrict__ aL) {
    long row = blockIdx.x;
    int t = (int)(row % Tq), tid = threadIdx.x;
    const float* p = w + row*(long)Tq;
    __shared__ float red[256];
    float vals[4], vmax = -1e30f;
#pragma unroll
    for (int i = 0; i < 4; i++) {
        int j = tid + i*256; float x = p[j]; vals[i] = x;
        if (j <= t && x > vmax) vmax = x;
    }
    red[tid] = vmax; __syncthreads();
    for (int s = 128; s > 0; s >>= 1) { if (tid < s) red[tid] = fmaxf(red[tid], red[tid+s]); __syncthreads(); }
    vmax = red[0]; __syncthreads();
    float sum = 0.f;
#pragma unroll
    for (int i = 0; i < 4; i++) {
        int j = tid + i*256;
        float e = (j <= t) ? expf(vals[i] - vmax) : 0.f;
        vals[i] = e; sum += e;
    }
    red[tid] = sum; __syncthreads();
    for (int s = 128; s > 0; s >>= 1) { if (tid < s) red[tid] += red[tid+s]; __syncthreads(); }
    float inv = 1.f / red[0];
#pragma unroll
    for (int i = 0; i < 4; i++) {
        bf16 h, l; split_bf(vals[i]*inv, h, l);
        long o = row*(long)Tq + tid + i*256;
        aH[o] = h; aL[o] = l;
    }
}

// --- residual+LN: t = x(+y); out = ln_only ? ln(t) : t+ln(t); optional hi/lo -
__global__ void resln(const float* __restrict__ x, const float* __restrict__ y,
                      const float* __restrict__ g, const float* __restrict__ b,
                      float* __restrict__ out, bf16* __restrict__ oh, bf16* __restrict__ ol, int ln_only) {
    long row = blockIdx.x;
    int tid = threadIdx.x;
    const float* px = x + row*(long)Dq;
    const float* py = y ? y + row*(long)Dq : nullptr;
    __shared__ float sh[Dq];
    __shared__ float red[256];
    float ls = 0.f;
    for (int i = tid; i < Dq; i += 256) { float t = px[i] + (py ? py[i] : 0.f); sh[i] = t; ls += t; }
    red[tid] = ls; __syncthreads();
    for (int s = 128; s > 0; s >>= 1) { if (tid < s) red[tid] += red[tid+s]; __syncthreads(); }
    float mean = red[0] * (1.0f/Dq); __syncthreads();
    float lv = 0.f;
    for (int i = tid; i < Dq; i += 256) { float d = sh[i]-mean; lv += d*d; }
    red[tid] = lv; __syncthreads();
    for (int s = 128; s > 0; s >>= 1) { if (tid < s) red[tid] += red[tid+s]; __syncthreads(); }
    float rstd = rsqrtf(red[0]*(1.0f/Dq) + 1e-5f);
    for (int i = tid; i < Dq; i += 256) {
        float t = sh[i];
        float l = (t - mean)*rstd*g[i] + b[i];
        float o = ln_only ? l : t + l;
        long oi = row*(long)Dq + i;
        if (out) out[oi] = o;
        if (oh) { bf16 hh, ll; split_bf(o, hh, ll); oh[oi] = hh; ol[oi] = ll; }
    }
}

// -----------------------------------------------------------------------------
extern "C" void kernel_launch(void* const* d_in, const int* in_sizes, int n_in,
                              void* d_out, int out_size)
{
    const float* src=(const float*)d_in[0]; const float* att=(const float*)d_in[1];
    const float* mWq=(const float*)d_in[2]; const float* mbq=(const float*)d_in[3];
    const float* mWk=(const float*)d_in[4]; const float* mbk=(const float*)d_in[5];
    const float* mWv=(const float*)d_in[6]; const float* dWp=(const float*)d_in[7];
    const float* dbp=(const float*)d_in[8]; const float* dWo=(const float*)d_in[9];
    const float* dbo=(const float*)d_in[10]; const float* fW1=(const float*)d_in[11];
    const float* fb1=(const float*)d_in[12]; const float* fW2=(const float*)d_in[13];
    const float* fb2=(const float*)d_in[14]; const float* g1=(const float*)d_in[15];
    const float* b1=(const float*)d_in[16]; const float* g2=(const float*)d_in[17];
    const float* b2=(const float*)d_in[18];
    float* out = (float*)d_out;

#define SYM(T,p,s) T p; cudaGetSymbolAddress((void**)&p, s)
    SYM(bf16*,srcH,g_srcH); SYM(bf16*,srcL,g_srcL); SYM(bf16*,attH,g_attH); SYM(bf16*,attL,g_attL);
    SYM(bf16*,WqTH,g_WqTH); SYM(bf16*,WqTL,g_WqTL); SYM(bf16*,WkTH,g_WkTH); SYM(bf16*,WkTL,g_WkTL);
    SYM(bf16*,WvTH,g_WvTH); SYM(bf16*,WvTL,g_WvTL);
    SYM(bf16*,qH,g_qH); SYM(bf16*,qL,g_qL); SYM(bf16*,kH,g_kH); SYM(bf16*,kL,g_kL);
    SYM(float*,v,g_v); SYM(bf16*,vTH,g_vTH); SYM(bf16*,vTL,g_vTL);
    SYM(float*,w,g_w); SYM(bf16*,aH,g_aH); SYM(bf16*,aL,g_aL);
    SYM(float*,ocat,g_ocat); SYM(float*,srcA,g_srcA); SYM(bf16*,srcAH,g_srcAH); SYM(bf16*,srcAL,g_srcAL);
    SYM(bf16*,dWpTH,g_dWpTH); SYM(bf16*,dWpTL,g_dWpTL); SYM(bf16*,wpH,g_wpH); SYM(bf16*,wpL,g_wpL);
    SYM(bf16*,o2H,g_o2H); SYM(bf16*,o2L,g_o2L); SYM(bf16*,dWoTH,g_dWoTH); SYM(bf16*,dWoTL,g_dWoTL);
    SYM(float*,o3,g_o3); SYM(float*,trgf,g_trgf); SYM(bf16*,ln2H,g_ln2H); SYM(bf16*,ln2L,g_ln2L);
    SYM(bf16*,fW1TH,g_fW1TH); SYM(bf16*,fW1TL,g_fW1TL); SYM(bf16*,h1H,g_h1H); SYM(bf16*,h1L,g_h1L);
    SYM(bf16*,fW2TH,g_fW2TH); SYM(bf16*,fW2TL,g_fW2TL); SYM(float*,ff,g_ff);

    cudaFuncSetAttribute(gemm_tc, cudaFuncAttributeMaxDynamicSharedMemorySize, SMEMT);
    dim3 tb(32, 8);
    const long TT=(long)Tq*Tq, TD=(long)Tq*Dq, BTD=(long)BT*Dq, BTHS=(long)BT*HSq, BTT=(long)Bq*Tq*Tq;

    // operand prep
    conv_hl<<<BTD/1024, 256>>>((const float4*)src, srcH, srcL);
    conv_hl<<<BTHS/1024, 256>>>((const float4*)att, attH, attL);
    tconv<<<dim3(HSq/32, Dq/32, Hq), tb>>>(mWq, WqTH, WqTL, Dq, HSq);
    tconv<<<dim3(HSq/32, Dq/32, Hq), tb>>>(mWk, WkTH, WkTL, Dq, HSq);
    tconv<<<dim3(HSq/32, Dq/32, Hq), tb>>>(mWv, WvTH, WvTL, Dq, HSq);
    tconv<<<dim3(Dq/32, HSq/32, Hq), tb>>>(dWp, dWpTH, dWpTL, HSq, Dq);
    tconv<<<dim3(Dq/32, Dq/32, 1), tb>>>(dWo, dWoTH, dWoTL, Dq, Dq);
    tconv<<<dim3(FFq/32, Dq/32, 1), tb>>>(fW1, fW1TH, fW1TL, Dq, FFq);
    tconv<<<dim3(Dq/32, FFq/32, 1), tb>>>(fW2, fW2TH, fW2TL, FFq, Dq);

    // q,k,v projections: per head, [8192,1024] = src @ W^T
    gemm_tc<<<dim3(4,64,Hq), 256, SMEMT>>>(srcH, srcL, WqTH, WqTL, mbq, nullptr, qH, qL,
        Dq, HSq, 1, 0,0, HSq,0, BTHS,0, HSq, 1.0f, 0);
    gemm_tc<<<dim3(4,64,Hq), 256, SMEMT>>>(srcH, srcL, WkTH, WkTL, mbk, nullptr, kH, kL,
        Dq, HSq, 1, 0,0, HSq,0, BTHS,0, HSq, 1.0f, 0);
    gemm_tc<<<dim3(4,64,Hq), 256, SMEMT>>>(srcH, srcL, WvTH, WvTL, nullptr, v, nullptr, nullptr,
        Dq, HSq, 1, 0,0, HSq,0, BTHS,0, 0, 1.0f, 0);
    tconv<<<dim3(HSq/32, Tq/32, Hq*Bq), tb>>>(v, vTH, vTL, Tq, HSq);
    // scores: per (h,b), [1024,1024] = q @ k^T * 32
    gemm_tc<<<dim3(4,8,Hq*Bq), 256, SMEMT>>>(qH, qL, kH, kL, nullptr, w, nullptr, nullptr,
        HSq, Tq, Bq, BT,Tq, BT,Tq, BTT,TT, 0, 32.0f, 0);
    softmax_causal<<<Hq*Bq*Tq, 256>>>(w, aH, aL);
    // o = a @ vT^T : per (h,b)
    gemm_tc<<<dim3(4,8,Hq*Bq), 256, SMEMT>>>(aH, aL, vTH, vTL, nullptr, ocat, nullptr, nullptr,
        Tq, Dq, Bq, Bq*Tq,Tq, Bq*HSq,HSq, (long)HSq,TD, 0, 1.0f, 0);
    resln<<<BT, 256>>>(src, ocat, g1, b1, srcA, srcAH, srcAL, 0);
    // wp = att @ dWp^T : per head [8192,4096]
    gemm_tc<<<dim3(16,64,Hq), 256, SMEMT>>>(attH, attL, dWpTH, dWpTL, dbp, nullptr, wpH, wpL,
        HSq, Dq, 1, 0,0, Dq,0, BTD,0, Dq, 1.0f, 0);
    // o2 = wp @ srcA^T : per (h,b), [1024,1024], K=4096
    gemm_tc<<<dim3(4,8,Hq*Bq), 256, SMEMT>>>(wpH, wpL, srcAH, srcAL, nullptr, nullptr, o2H, o2L,
        Dq, Dq, Bq, BT,Tq, 0,Tq, (long)Tq,TD, 0, 1.0f, 0);
    // o3 = o2 @ dWo^T
    gemm_tc<<<dim3(16,64,1), 256, SMEMT>>>(o2H, o2L, dWoTH, dWoTL, dbo, o3, nullptr, nullptr,
        Dq, Dq, 1, 0,0, 0,0, 0,0, 0, 1.0f, 0);
    resln<<<BT, 256>>>(srcA, o3, g1, b1, trgf, nullptr, nullptr, 0);
    resln<<<BT, 256>>>(trgf, nullptr, g2, b2, nullptr, ln2H, ln2L, 1);
    // h1 = gelu(ln2 @ fW1^T + fb1)
    gemm_tc<<<dim3(80,64,1), 256, SMEMT>>>(ln2H, ln2L, fW1TH, fW1TL, fb1, nullptr, h1H, h1L,
        Dq, FFq, 1, 0,0, 0,0, 0,0, 0, 1.0f, 1);
    // ff = h1 @ fW2^T + fb2
    gemm_tc<<<dim3(16,64,1), 256, SMEMT>>>(h1H, h1L, fW2TH, fW2TL, fb2, ff, nullptr, nullptr,
        FFq, Dq, 1, 0,0, 0,0, 0,0, 0, 1.0f, 0);
    resln<<<BT, 256>>>(trgf, ff, g2, b2, out, nullptr, nullptr, 1);
}